// round 5
// baseline (speedup 1.0000x reference)
#include <cuda_runtime.h>
#include <cuda_bf16.h>
#include <math.h>

// ---------------------------------------------------------------------------
// Problem constants
// ---------------------------------------------------------------------------
#define BB   4
#define SS   2048
#define DD   768
#define HH   8
#define HD   96
#define EXPN 4
#define DFF  (DD * EXPN)     // 3072
#define MM   (BB * SS)       // 8192 rows
#define LN_EPS 1e-5f

// ---------------------------------------------------------------------------
// Scratch (device globals; no allocations allowed)
// ---------------------------------------------------------------------------
__device__ float g_q [MM * DD];
__device__ float g_k [MM * DD];
__device__ float g_v [MM * DD];
__device__ float g_o [MM * DD];
__device__ float g_x1[MM * DD];
__device__ float g_h [MM * DFF];

// ---------------------------------------------------------------------------
// Packed f32x2 helpers (FFMA2 — PTX-only, ptxas won't auto-fuse)
// ---------------------------------------------------------------------------
__device__ __forceinline__ unsigned long long bcast2(float a) {
    unsigned long long r;
    asm("mov.b64 %0, {%1, %1};" : "=l"(r) : "f"(a));
    return r;
}
__device__ __forceinline__ unsigned long long ffma2(
    unsigned long long a, unsigned long long b, unsigned long long c)
{
    unsigned long long d;
    asm("fma.rn.f32x2 %0, %1, %2, %3;" : "=l"(d) : "l"(a), "l"(b), "l"(c));
    return d;
}

// ---------------------------------------------------------------------------
// GELU (tanh approximation, matches jax.nn.gelu default)
// ---------------------------------------------------------------------------
__device__ __forceinline__ float gelu_f(float x) {
    float x3 = x * x * x;
    float t  = tanhf(0.7978845608028654f * (x + 0.044715f * x3));
    return 0.5f * x * (1.0f + t);
}

// ---------------------------------------------------------------------------
// SGEMM: C[M,N] = A[M,K] @ B[K,N] + bias (optional GELU epilogue)
// 128x128 block tile, BK=16, 256 threads, 8x8 per-thread microtile computed
// as 8x4 packed f32x2 pairs, double-buffered shared memory.
// M,N multiples of 128; K multiple of 16.
// ---------------------------------------------------------------------------
template<int GELU>
__global__ __launch_bounds__(256) void sgemm_kernel(
    const float* __restrict__ A, const float* __restrict__ B,
    const float* __restrict__ bias, float* __restrict__ C,
    int M, int N, int K)
{
    constexpr int BM = 128, BN = 128, BK = 16;
    __shared__ float As[2][BK][BM];   // stored transposed: As[k][m]
    __shared__ float Bs[2][BK][BN];

    const int tid = threadIdx.x;
    const int tx  = tid & 15;         // col group (8 cols)
    const int ty  = tid >> 4;         // row group (8 rows)
    const int row0 = blockIdx.y * BM;
    const int col0 = blockIdx.x * BN;

    // A tile loads: 512 float4; thread does f4 #tid and #(tid+256)
    const int a_r0 = tid >> 2;              // 0..63
    const int a_k0 = (tid & 3) << 2;        // 0,4,8,12
    // B tile loads
    const int b_k0 = tid >> 5;              // 0..7
    const int b_n0 = (tid & 31) << 2;       // 0..124

    const float* Ap = A + (size_t)row0 * K;
    const float* Bp = B + col0;

    float4 ra0, ra1, rb0, rb1;

    // prologue: tile 0
    {
        ra0 = *(const float4*)(Ap + (size_t)a_r0        * K + a_k0);
        ra1 = *(const float4*)(Ap + (size_t)(a_r0 + 64) * K + a_k0);
        rb0 = *(const float4*)(Bp + (size_t)b_k0       * N + b_n0);
        rb1 = *(const float4*)(Bp + (size_t)(b_k0 + 8) * N + b_n0);
        As[0][a_k0+0][a_r0] = ra0.x; As[0][a_k0+1][a_r0] = ra0.y;
        As[0][a_k0+2][a_r0] = ra0.z; As[0][a_k0+3][a_r0] = ra0.w;
        As[0][a_k0+0][a_r0+64] = ra1.x; As[0][a_k0+1][a_r0+64] = ra1.y;
        As[0][a_k0+2][a_r0+64] = ra1.z; As[0][a_k0+3][a_r0+64] = ra1.w;
        *(float4*)&Bs[0][b_k0  ][b_n0] = rb0;
        *(float4*)&Bs[0][b_k0+8][b_n0] = rb1;
    }
    __syncthreads();

    // accumulators: 8 rows x 4 packed col-pairs (= 8x8 floats)
    unsigned long long acc2[8][4];
    #pragma unroll
    for (int i = 0; i < 8; i++)
        #pragma unroll
        for (int p = 0; p < 4; p++) acc2[i][p] = 0ull;

    const int nk = K / BK;
    for (int kt = 0; kt < nk; ++kt) {
        const int cur = kt & 1;
        if (kt + 1 < nk) {
            const int kb = (kt + 1) * BK;
            ra0 = *(const float4*)(Ap + (size_t)a_r0        * K + kb + a_k0);
            ra1 = *(const float4*)(Ap + (size_t)(a_r0 + 64) * K + kb + a_k0);
            rb0 = *(const float4*)(Bp + (size_t)(kb + b_k0    ) * N + b_n0);
            rb1 = *(const float4*)(Bp + (size_t)(kb + b_k0 + 8) * N + b_n0);
        }
        #pragma unroll
        for (int kk = 0; kk < BK; ++kk) {
            float af[8];
            *(float4*)&af[0] = *(const float4*)&As[cur][kk][ty * 8];
            *(float4*)&af[4] = *(const float4*)&As[cur][kk][ty * 8 + 4];
            // B pairs are adjacent floats -> free 64-bit lanes
            ulonglong2 blo = *(const ulonglong2*)&Bs[cur][kk][tx * 8];
            ulonglong2 bhi = *(const ulonglong2*)&Bs[cur][kk][tx * 8 + 4];
            unsigned long long bb[4] = { blo.x, blo.y, bhi.x, bhi.y };
            #pragma unroll
            for (int i = 0; i < 8; i++) {
                unsigned long long aa = bcast2(af[i]);
                #pragma unroll
                for (int p = 0; p < 4; p++)
                    acc2[i][p] = ffma2(aa, bb[p], acc2[i][p]);
            }
        }
        if (kt + 1 < nk) {
            const int nxt = cur ^ 1;
            As[nxt][a_k0+0][a_r0] = ra0.x; As[nxt][a_k0+1][a_r0] = ra0.y;
            As[nxt][a_k0+2][a_r0] = ra0.z; As[nxt][a_k0+3][a_r0] = ra0.w;
            As[nxt][a_k0+0][a_r0+64] = ra1.x; As[nxt][a_k0+1][a_r0+64] = ra1.y;
            As[nxt][a_k0+2][a_r0+64] = ra1.z; As[nxt][a_k0+3][a_r0+64] = ra1.w;
            *(float4*)&Bs[nxt][b_k0  ][b_n0] = rb0;
            *(float4*)&Bs[nxt][b_k0+8][b_n0] = rb1;
        }
        __syncthreads();
    }

    // epilogue: bias (+ GELU) and store
    const int ccol = col0 + tx * 8;
    float bvals[8];
    *(float4*)&bvals[0] = *(const float4*)&bias[ccol];
    *(float4*)&bvals[4] = *(const float4*)&bias[ccol + 4];
    #pragma unroll
    for (int i = 0; i < 8; i++) {
        float out[8];
        #pragma unroll
        for (int p = 0; p < 4; p++) {
            float2 f = *(float2*)&acc2[i][p];
            float v0 = f.x + bvals[2*p];
            float v1 = f.y + bvals[2*p + 1];
            if (GELU) { v0 = gelu_f(v0); v1 = gelu_f(v1); }
            out[2*p]     = v0;
            out[2*p + 1] = v1;
        }
        float* Cp = C + (size_t)(row0 + ty * 8 + i) * N + ccol;
        *(float4*)Cp       = *(float4*)&out[0];
        *(float4*)(Cp + 4) = *(float4*)&out[4];
    }
}

// ---------------------------------------------------------------------------
// Flash attention: per (b,h), BQ=64 query tile, stream K/V in BK=64 tiles,
// online softmax, 128 threads (16 row-groups x 8 col-groups).
// ---------------------------------------------------------------------------
#define ATT_BQ 64
#define ATT_BK 64
#define ATT_NT 128
#define ATT_QP 97   // padded row stride for Q/K/V tiles
#define ATT_PP 65   // padded row stride for P tile

#define ATT_SMEM_FLOATS (ATT_BQ*ATT_QP + 2*ATT_BK*ATT_QP + ATT_BQ*ATT_PP)
#define ATT_SMEM_BYTES  (ATT_SMEM_FLOATS * 4)

__global__ __launch_bounds__(128) void flash_attn_kernel(
    const float* __restrict__ Q, const float* __restrict__ K,
    const float* __restrict__ V, float* __restrict__ O)
{
    extern __shared__ float sm[];
    float* Qs = sm;                          // ATT_BQ * ATT_QP
    float* Ks = Qs + ATT_BQ * ATT_QP;        // ATT_BK * ATT_QP
    float* Vs = Ks + ATT_BK * ATT_QP;        // ATT_BK * ATT_QP
    float* Ps = Vs + ATT_BK * ATT_QP;        // ATT_BQ * ATT_PP

    const int tid = threadIdx.x;
    const int tx  = tid & 7;                 // 8 col groups (8 cols each)
    const int ty  = tid >> 3;                // 16 row groups (4 rows each)
    const int row_q = ty * 4;

    const int q0 = blockIdx.x * ATT_BQ;
    const int bh = blockIdx.y;
    const int b  = bh >> 3;
    const int h  = bh & 7;

    const float scale = 0.10206207261596577f;   // 96^-0.5

    const float* Qg = Q + (size_t)(b * SS + q0) * DD + h * HD;
    for (int i = tid; i < ATT_BQ * HD; i += ATT_NT) {
        int r = i / HD, c = i - r * HD;
        Qs[r * ATT_QP + c] = Qg[(size_t)r * DD + c] * scale;
    }

    float m[4], l[4], o[4][12];
    #pragma unroll
    for (int r = 0; r < 4; r++) {
        m[r] = -1e30f; l[r] = 0.0f;
        #pragma unroll
        for (int d = 0; d < 12; d++) o[r][d] = 0.0f;
    }

    for (int kt = 0; kt < SS / ATT_BK; ++kt) {
        const float* Kg = K + (size_t)(b * SS + kt * ATT_BK) * DD + h * HD;
        const float* Vg = V + (size_t)(b * SS + kt * ATT_BK) * DD + h * HD;
        __syncthreads();   // previous iteration's reads of Ks/Vs/Ps done
        for (int i = tid; i < ATT_BK * HD; i += ATT_NT) {
            int r = i / HD, c = i - r * HD;
            Ks[r * ATT_QP + c] = Kg[(size_t)r * DD + c];
            Vs[r * ATT_QP + c] = Vg[(size_t)r * DD + c];
        }
        __syncthreads();

        // --- GEMM1: S = Qs @ Ks^T (scale already folded into Qs) ---
        float s[4][8];
        #pragma unroll
        for (int r = 0; r < 4; r++)
            #pragma unroll
            for (int c = 0; c < 8; c++) s[r][c] = 0.0f;

        #pragma unroll 8
        for (int dd = 0; dd < HD; ++dd) {
            float qv[4], kv[8];
            #pragma unroll
            for (int r = 0; r < 4; r++) qv[r] = Qs[(row_q + r) * ATT_QP + dd];
            #pragma unroll
            for (int c = 0; c < 8; c++) kv[c] = Ks[(tx * 8 + c) * ATT_QP + dd];
            #pragma unroll
            for (int r = 0; r < 4; r++)
                #pragma unroll
                for (int c = 0; c < 8; c++)
                    s[r][c] = fmaf(qv[r], kv[c], s[r][c]);
        }

        // --- online softmax update (row spread over 8 lanes: same ty) ---
        #pragma unroll
        for (int r = 0; r < 4; r++) {
            float mx = s[r][0];
            #pragma unroll
            for (int c = 1; c < 8; c++) mx = fmaxf(mx, s[r][c]);
            mx = fmaxf(mx, __shfl_xor_sync(0xffffffffu, mx, 1));
            mx = fmaxf(mx, __shfl_xor_sync(0xffffffffu, mx, 2));
            mx = fmaxf(mx, __shfl_xor_sync(0xffffffffu, mx, 4));
            float mnew  = fmaxf(m[r], mx);
            float alpha = __expf(m[r] - mnew);
            float rs = 0.0f;
            #pragma unroll
            for (int c = 0; c < 8; c++) {
                float p = __expf(s[r][c] - mnew);
                s[r][c] = p;
                rs += p;
            }
            rs += __shfl_xor_sync(0xffffffffu, rs, 1);
            rs += __shfl_xor_sync(0xffffffffu, rs, 2);
            rs += __shfl_xor_sync(0xffffffffu, rs, 4);
            l[r] = l[r] * alpha + rs;
            m[r] = mnew;
            #pragma unroll
            for (int d = 0; d < 12; d++) o[r][d] *= alpha;
            #pragma unroll
            for (int c = 0; c < 8; c++)
                Ps[(row_q + r) * ATT_PP + tx * 8 + c] = s[r][c];
        }
        __syncthreads();

        // --- GEMM2: O += P @ V  (thread owns rows row_q..+3, dims tx*12..+11) ---
        #pragma unroll 4
        for (int j = 0; j < ATT_BK; ++j) {
            float pv[4], vv[12];
            #pragma unroll
            for (int r = 0; r < 4; r++) pv[r] = Ps[(row_q + r) * ATT_PP + j];
            #pragma unroll
            for (int d = 0; d < 12; d++) vv[d] = Vs[j * ATT_QP + tx * 12 + d];
            #pragma unroll
            for (int r = 0; r < 4; r++)
                #pragma unroll
                for (int d = 0; d < 12; d++)
                    o[r][d] = fmaf(pv[r], vv[d], o[r][d]);
        }
    }

    float* Og = O + (size_t)(b * SS + q0) * DD + h * HD;
    #pragma unroll
    for (int r = 0; r < 4; r++) {
        float inv = 1.0f / l[r];
        #pragma unroll
        for (int d = 0; d < 12; d++)
            Og[(size_t)(row_q + r) * DD + tx * 12 + d] = o[r][d] * inv;
    }
}

// ---------------------------------------------------------------------------
// Fused residual-add + LayerNorm over rows of 768
// ---------------------------------------------------------------------------
__global__ __launch_bounds__(256) void add_ln_kernel(
    const float* __restrict__ a, const float* __restrict__ rsd,
    const float* __restrict__ g, const float* __restrict__ be,
    float* __restrict__ out)
{
    __shared__ float buf[DD];
    __shared__ float wred[16];
    __shared__ float stats[2];
    const int row = blockIdx.x;
    const int tid = threadIdx.x;
    const size_t off = (size_t)row * DD;

    float s = 0.0f, s2 = 0.0f;
    for (int i = tid; i < DD; i += 256) {
        float v = a[off + i] + rsd[off + i];
        buf[i] = v;
        s  += v;
        s2 += v * v;
    }
    #pragma unroll
    for (int o = 16; o > 0; o >>= 1) {
        s  += __shfl_xor_sync(0xffffffffu, s,  o);
        s2 += __shfl_xor_sync(0xffffffffu, s2, o);
    }
    const int w = tid >> 5;
    if ((tid & 31) == 0) { wred[w] = s; wred[8 + w] = s2; }
    __syncthreads();
    if (tid == 0) {
        float S = 0.0f, S2 = 0.0f;
        #pragma unroll
        for (int i = 0; i < 8; i++) { S += wred[i]; S2 += wred[8 + i]; }
        float mu  = S * (1.0f / DD);
        float var = S2 * (1.0f / DD) - mu * mu;
        stats[0] = mu;
        stats[1] = rsqrtf(var + LN_EPS);
    }
    __syncthreads();
    const float mu = stats[0], rstd = stats[1];
    for (int i = tid; i < DD; i += 256)
        out[off + i] = (buf[i] - mu) * rstd * g[i] + be[i];
}

// ---------------------------------------------------------------------------
// kernel_launch
// inputs: x, Wq, bq, Wk, bk, Wv, bv, Wo, bo, g1, be1, W1, bf1, W2, bf2, g2, be2
// ---------------------------------------------------------------------------
extern "C" void kernel_launch(void* const* d_in, const int* in_sizes, int n_in,
                              void* d_out, int out_size)
{
    const float* x   = (const float*)d_in[0];
    const float* Wq  = (const float*)d_in[1];
    const float* bq  = (const float*)d_in[2];
    const float* Wk  = (const float*)d_in[3];
    const float* bk  = (const float*)d_in[4];
    const float* Wv  = (const float*)d_in[5];
    const float* bv  = (const float*)d_in[6];
    const float* Wo  = (const float*)d_in[7];
    const float* bo  = (const float*)d_in[8];
    const float* g1  = (const float*)d_in[9];
    const float* be1 = (const float*)d_in[10];
    const float* W1  = (const float*)d_in[11];
    const float* bf1 = (const float*)d_in[12];
    const float* W2  = (const float*)d_in[13];
    const float* bf2 = (const float*)d_in[14];
    const float* g2  = (const float*)d_in[15];
    const float* be2 = (const float*)d_in[16];
    float* out = (float*)d_out;

    float *q, *k, *v, *o, *x1, *hb;
    cudaGetSymbolAddress((void**)&q,  g_q);
    cudaGetSymbolAddress((void**)&k,  g_k);
    cudaGetSymbolAddress((void**)&v,  g_v);
    cudaGetSymbolAddress((void**)&o,  g_o);
    cudaGetSymbolAddress((void**)&x1, g_x1);
    cudaGetSymbolAddress((void**)&hb, g_h);

    const dim3 thr(256);
    const dim3 grd_d (DD  / 128, MM / 128);   // (6, 64)
    const dim3 grd_ff(DFF / 128, MM / 128);   // (24, 64)

    // QKV projections
    sgemm_kernel<0><<<grd_d, thr>>>(x, Wq, bq, q, MM, DD, DD);
    sgemm_kernel<0><<<grd_d, thr>>>(x, Wk, bk, k, MM, DD, DD);
    sgemm_kernel<0><<<grd_d, thr>>>(x, Wv, bv, v, MM, DD, DD);

    // attention
    cudaFuncSetAttribute(flash_attn_kernel,
                         cudaFuncAttributeMaxDynamicSharedMemorySize,
                         ATT_SMEM_BYTES);
    flash_attn_kernel<<<dim3(SS / ATT_BQ, BB * HH), ATT_NT, ATT_SMEM_BYTES>>>(q, k, v, o);

    // output projection (reuse q as attn_out)
    sgemm_kernel<0><<<grd_d, thr>>>(o, Wo, bo, q, MM, DD, DD);

    // residual + LN1 -> x1
    add_ln_kernel<<<MM, thr>>>(q, x, g1, be1, x1);

    // FFN
    sgemm_kernel<1><<<grd_ff, thr>>>(x1, W1, bf1, hb, MM, DFF, DD);
    sgemm_kernel<0><<<grd_d,  thr>>>(hb, W2, bf2, k,  MM, DD, DFF);   // reuse k

    // residual + LN2 -> out
    add_ln_kernel<<<MM, thr>>>(k, x1, g2, be2, out);
}